// round 9
// baseline (speedup 1.0000x reference)
#include <cuda_runtime.h>
#include <math.h>
#include <stdint.h>

#define Bsz 1024
#define Nn  100
#define Hh  256
#define H3  768
#define NBLK 128
#define NT  512
#define CLSZ 8
#define HROW 260   // padded row stride (floats) for h buffer
#define WROW 264   // padded row stride (floats) for weight slices

// ---------------- static device scratch ----------------
__device__ float g_G[Bsz*Nn*H3];      // enc @ W1T + b_ih1
__device__ float g_ref[Bsz*Nn*Hh];    // enc @ W_ref
__device__ float g_G0[Bsz*H3];
__device__ float g_mean[Bsz*Hh];
__device__ float g_W1T[Hh*H3];        // [k][j] for precompute GEMM
__device__ float g_bias0[H3];
__device__ float g_wD[H3];

// ---------------- math helpers ----------------
__device__ __forceinline__ float fast_tanh(float x) {
    float ax = fabsf(x);
    float e  = __expf(-2.0f * ax);
    float t  = __fdividef(1.0f - e, 1.0f + e);
    return copysignf(t, x);
}
__device__ __forceinline__ float sigmoidf_(float x) {
    return __fdividef(1.0f, 1.0f + __expf(-x));
}
__device__ __forceinline__ float tanh4dot(float4 q, float4 r, float4 v) {
    const float C = -2.8853900817779268f;   // -2*log2(e)
    float x0=q.x+r.x, x1=q.y+r.y, x2=q.z+r.z, x3=q.w+r.w;
    float e0=exp2f(fabsf(x0)*C), e1=exp2f(fabsf(x1)*C);
    float e2=exp2f(fabsf(x2)*C), e3=exp2f(fabsf(x3)*C);
    float a0=1.f+e0, a1=1.f+e1, a2=1.f+e2, a3=1.f+e3;
    float m0=(1.f-e0)*v.x, m1=(1.f-e1)*v.y, m2=(1.f-e2)*v.z, m3=(1.f-e3)*v.w;
    m0=__uint_as_float(__float_as_uint(m0)^(__float_as_uint(x0)&0x80000000u));
    m1=__uint_as_float(__float_as_uint(m1)^(__float_as_uint(x1)&0x80000000u));
    m2=__uint_as_float(__float_as_uint(m2)^(__float_as_uint(x2)&0x80000000u));
    m3=__uint_as_float(__float_as_uint(m3)^(__float_as_uint(x3)&0x80000000u));
    float p01=a0*a1, p23=a2*a3, d=p01*p23, rd;
    asm("rcp.approx.f32 %0, %1;" : "=f"(rd) : "f"(d));
    float num = fmaf(fmaf(m0,a1,m1*a0), p23, fmaf(m2,a3,m3*a2)*p01);
    return num * rd;
}
__device__ __forceinline__ float dot4(float4 a, float4 b, float acc) {
    acc = fmaf(a.x, b.x, acc); acc = fmaf(a.y, b.y, acc);
    acc = fmaf(a.z, b.z, acc); acc = fmaf(a.w, b.w, acc);
    return acc;
}

// ---------------- cluster / DSMEM helpers ----------------
__device__ __forceinline__ uint32_t smem_u32(const void* p) {
    uint32_t a;
    asm("{ .reg .u64 t; cvta.to.shared.u64 t, %1; cvt.u32.u64 %0, t; }" : "=r"(a) : "l"(p));
    return a;
}
__device__ __forceinline__ uint32_t ctarank() {
    uint32_t r; asm("mov.u32 %0, %%cluster_ctarank;" : "=r"(r)); return r;
}
__device__ __forceinline__ void stc32(uint32_t laddr, uint32_t rank, float v) {
    asm volatile("{ .reg .b32 ra; mapa.shared::cluster.u32 ra, %0, %1;"
                 " st.shared::cluster.b32 [ra], %2; }"
                 :: "r"(laddr), "r"(rank), "r"(__float_as_uint(v)) : "memory");
}
__device__ __forceinline__ void mbar_init(uint32_t a, uint32_t cnt) {
    asm volatile("mbarrier.init.shared.b64 [%0], %1;" :: "r"(a), "r"(cnt) : "memory");
}
__device__ __forceinline__ void fence_cluster() {
    asm volatile("fence.acq_rel.cluster;" ::: "memory");
}
__device__ __forceinline__ void mbar_arrive_rank(uint32_t la, uint32_t r) {
    asm volatile("{ .reg .b32 ra; mapa.shared::cluster.u32 ra, %0, %1;"
                 " mbarrier.arrive.release.cluster.shared::cluster.b64 _, [ra]; }"
                 :: "r"(la), "r"(r) : "memory");
}
__device__ __forceinline__ void mbar_wait(uint32_t a, uint32_t par) {
    asm volatile("{ .reg .pred P; WL%=:"
                 " mbarrier.try_wait.parity.acquire.cluster.shared::cta.b64 P, [%0], %1, 0x989680;"
                 " @P bra WD%=; bra WL%=; WD%=: }"
                 :: "r"(a), "r"(par) : "memory");
}
#define CLUSTER_SYNC_() do { \
    asm volatile("barrier.cluster.arrive.aligned;" ::: "memory"); \
    asm volatile("barrier.cluster.wait.aligned;" ::: "memory"); } while (0)

// ---------------- precompute kernels ----------------
__global__ void k_prep(const float* __restrict__ W_ih1, const float* __restrict__ b_ih1) {
    int i = blockIdx.x * 256 + threadIdx.x;    // 768 blocks -> 196608
    if (i < Hh*H3) {
        int k = i / H3, j = i % H3;
        g_W1T[i] = W_ih1[j*257 + k];
    }
    if (i < H3) {
        float wd = W_ih1[i*257 + 256];
        g_wD[i] = wd;
        g_bias0[i] = b_ih1[i] + wd;
    }
}

__global__ void k_mean(const float* __restrict__ enc) {
    int b = blockIdx.x, h = threadIdx.x;
    float s = 0.f;
    for (int n = 0; n < Nn; n++) s += enc[(b*Nn + n)*Hh + h];
    g_mean[b*Hh + h] = s / (float)Nn;
}

template<int BM, int BN, int TM, int TN>
__global__ __launch_bounds__(256)
void k_sgemm(const float* __restrict__ A, const float* __restrict__ Bm,
             const float* __restrict__ bias, float* __restrict__ C,
             int M, int N, int K) {
    const int BK = 16;
    __shared__ float As[BK][BM];
    __shared__ float Bs[BK][BN];
    int tid = threadIdx.x;
    int tx = tid % (BN/TN), ty = tid / (BN/TN);
    int m0 = blockIdx.y * BM, n0 = blockIdx.x * BN;
    float acc[TM][TN];
#pragma unroll
    for (int i = 0; i < TM; i++)
#pragma unroll
        for (int j = 0; j < TN; j++) acc[i][j] = 0.f;
    for (int k0 = 0; k0 < K; k0 += BK) {
#pragma unroll
        for (int r = 0; r < (BM*BK)/1024; r++) {
            int idx = tid + r*256, mm = idx/(BK/4), kk4 = idx%(BK/4);
            float4 a = *(const float4*)&A[(size_t)(m0+mm)*K + k0 + kk4*4];
            As[kk4*4+0][mm]=a.x; As[kk4*4+1][mm]=a.y; As[kk4*4+2][mm]=a.z; As[kk4*4+3][mm]=a.w;
        }
#pragma unroll
        for (int r = 0; r < (BK*BN)/1024; r++) {
            int idx = tid + r*256, kk = idx/(BN/4), nn4 = idx%(BN/4);
            *(float4*)&Bs[kk][nn4*4] = *(const float4*)&Bm[(size_t)(k0+kk)*N + n0 + nn4*4];
        }
        __syncthreads();
#pragma unroll
        for (int kk = 0; kk < BK; kk++) {
            float ra[TM], rb[TN];
#pragma unroll
            for (int i = 0; i < TM; i += 4) *(float4*)&ra[i] = *(float4*)&As[kk][ty*TM+i];
#pragma unroll
            for (int j = 0; j < TN; j += 4) *(float4*)&rb[j] = *(float4*)&Bs[kk][tx*TN+j];
#pragma unroll
            for (int i = 0; i < TM; i++)
#pragma unroll
                for (int j = 0; j < TN; j++) acc[i][j] += ra[i]*rb[j];
        }
        __syncthreads();
    }
#pragma unroll
    for (int i = 0; i < TM; i++) {
        int m = m0 + ty*TM + i;
#pragma unroll
        for (int j = 0; j < TN; j += 4) {
            int n = n0 + tx*TN + j;
            float4 r;
            r.x = acc[i][j+0] + (bias ? bias[n+0] : 0.f);
            r.y = acc[i][j+1] + (bias ? bias[n+1] : 0.f);
            r.z = acc[i][j+2] + (bias ? bias[n+2] : 0.f);
            r.w = acc[i][j+3] + (bias ? bias[n+3] : 0.f);
            *(float4*)&C[(size_t)m*N + n] = r;
        }
    }
}

// ---------------- cluster decode loop ----------------
// smem float offsets:
#define OF_HB   0                          // hbuf: 64 x 260
#define OF_W2S  (OF_HB + 64*HROW)          // 16640 : W2 slice [g][jj][k] 3 x 32 x 264
#define OF_WQS  (OF_W2S + 3*32*WROW)       // 41984 : Wq slice [jj][k] 32 x 264
#define OF_QB   (OF_WQS + 32*WROW)         // 50432 : qbuf 8 x 256
#define OF_SV   (OF_QB + 2048)             // 52480
#define OF_SU   (OF_SV + 256)              // 52736
#define OF_INT  (OF_SU + 800)              // 53536
// bytes after floats: nxt 32 | mask 800 | pi 800 | mbar 32
#define MBAR_OFF_BYTES (OF_INT*4 + 32 + 800 + 800)
#define SMEM_BYTES     (MBAR_OFF_BYTES + 32)

__global__ __launch_bounds__(NT, 1) __cluster_dims__(CLSZ, 1, 1)
void k_loop(const float* __restrict__ G,  const float* __restrict__ G0,
            const float* __restrict__ REF,
            const float* __restrict__ W_ih2, const float* __restrict__ W_q,
            const float* __restrict__ b_hh1,
            const float* __restrict__ b_ih2, const float* __restrict__ b_hh2,
            const float* __restrict__ v,   const float* __restrict__ wD,
            const float* __restrict__ x,   float* __restrict__ out) {
    extern __shared__ float sm[];
    float* hbuf = sm + OF_HB;
    float* w2s  = sm + OF_W2S;
    float* wqs  = sm + OF_WQS;
    float* qbuf = sm + OF_QB;
    float* sv   = sm + OF_SV;
    float* su   = sm + OF_SU;
    int*   nxt  = (int*)(sm + OF_INT);
    unsigned char* mask = (unsigned char*)(nxt + 8);
    unsigned char* pi   = mask + 800;

    const uint32_t base = smem_u32(sm);
    const uint32_t HBa  = base;
    const uint32_t QBa  = base + OF_QB*4;
    const uint32_t MB   = base + MBAR_OFF_BYTES;

    const int tid = threadIdx.x, lane = tid & 31, w = tid >> 5;
    const uint32_t rank = ctarank();
    const int b0 = blockIdx.x * 8;                    // my 8 global batch rows
    const int jt = tid >> 4, rg = tid & 15;           // GEMM mapping (rows rg+16r)

    // ---- one-time init ----
    for (int i = tid; i < 800; i += NT) mask[i] = 0;
    if (tid < 256) sv[tid] = __ldg(v + tid);
    for (int i = tid; i < 3*32*256; i += NT) {        // w2s[g][jj][k], padded rows
        int k = i & 255, jj = (i >> 8) & 31, g = i >> 13;
        w2s[g*(32*WROW) + jj*WROW + k] = __ldg(&W_ih2[(g*256 + (int)rank*32 + jj)*256 + k]);
    }
    for (int i = tid; i < 32*256; i += NT) {          // wqs[jj][k], padded rows
        int k = i & 255, jj = i >> 8;
        wqs[jj*WROW + k] = __ldg(&W_q[k*256 + (int)rank*32 + jj]);
    }
    const int j0 = (int)rank*32 + jt;                 // my h2/q column
    const float bi2r = __ldg(b_ih2 + j0),       bh2r = __ldg(b_hh2 + j0);
    const float bi2z = __ldg(b_ih2 + 256 + j0), bh2z = __ldg(b_hh2 + 256 + j0);
    const float bi2n = __ldg(b_ih2 + 512 + j0), bh2n = __ldg(b_hh2 + 512 + j0);

    if (tid == 0) {
#pragma unroll
        for (int b = 0; b < 4; b++) mbar_init(MB + b*8, CLSZ);
    }
    __syncthreads();
    CLUSTER_SYNC_();   // barriers visible cluster-wide before first arrive

    const uint32_t BAR_H1 = MB, BAR_FREE = MB + 8, BAR_H2 = MB + 16, BAR_Q = MB + 24;

    float Dv = 1.0f, ll = 0.0f;

#pragma unroll 1
    for (int t = 0; t < Nn; t++) {
        const uint32_t par = (uint32_t)(t & 1);

        // ---- A: GRU1 (h=0) for my 8 rows -> broadcast h1 to all CTAs ----
#pragma unroll
        for (int c = 0; c < 4; c++) {
            int idx = tid + c*NT;                  // 0..2047
            int row = idx >> 8, j = idx & 255;
            const float* gsrc = (t == 0) ? (G0 + (size_t)(b0 + row)*H3)
                                         : (G + ((size_t)(b0 + row)*Nn + nxt[row])*H3);
            float gr = __ldg(gsrc+j), gz = __ldg(gsrc+j+256), gn = __ldg(gsrc+j+512);
            if (t > 0) {
                gr = fmaf(Dv, __ldg(wD+j),     gr);
                gz = fmaf(Dv, __ldg(wD+j+256), gz);
                gn = fmaf(Dv, __ldg(wD+j+512), gn);
            }
            float rr = sigmoidf_(gr + __ldg(b_hh1+j));
            float zz = sigmoidf_(gz + __ldg(b_hh1+j+256));
            float nn = fast_tanh(fmaf(rr, __ldg(b_hh1+j+512), gn));
            float h1v = (1.f - zz) * nn;
            uint32_t la = HBa + (uint32_t)((((int)rank*8 + row)*HROW + j)*4);
#pragma unroll
            for (int p = 0; p < CLSZ; p++) stc32(la, p, h1v);
        }
        __syncthreads();
        if (tid < CLSZ) { fence_cluster(); mbar_arrive_rank(BAR_H1, tid); }
        mbar_wait(BAR_H1, par);

        // ---- B: gi2 = h1 @ W2 (my 32-col triplet slice), 64 rows ----
        float a0[4], a1[4], a2[4];
#pragma unroll
        for (int r = 0; r < 4; r++) { a0[r]=0.f; a1[r]=0.f; a2[r]=0.f; }
        {
            const float* w0 = w2s + jt*WROW;
            const float* w1 = w2s + 32*WROW + jt*WROW;
            const float* w2g = w2s + 64*WROW + jt*WROW;
#pragma unroll 4
            for (int k4 = 0; k4 < 64; k4++) {
                float4 bb0 = *(const float4*)(w0  + k4*4);
                float4 bb1 = *(const float4*)(w1  + k4*4);
                float4 bb2 = *(const float4*)(w2g + k4*4);
#pragma unroll
                for (int r = 0; r < 4; r++) {
                    float4 a = *(const float4*)&hbuf[(rg + 16*r)*HROW + k4*4];
                    a0[r] = dot4(a, bb0, a0[r]);
                    a1[r] = dot4(a, bb1, a1[r]);
                    a2[r] = dot4(a, bb2, a2[r]);
                }
            }
        }
        __syncthreads();                          // all done reading hbuf (h1)
        if (tid < CLSZ) { fence_cluster(); mbar_arrive_rank(BAR_FREE, tid); }
        // GRU2 into registers (overlaps the wait)
        float h2v[4];
#pragma unroll
        for (int r = 0; r < 4; r++) {
            float rr = sigmoidf_((a0[r] + bi2r) + bh2r);
            float zz = sigmoidf_((a1[r] + bi2z) + bh2z);
            float nn = fast_tanh(fmaf(rr, bh2n, a2[r] + bi2n));
            h2v[r] = (1.f - zz) * nn;
        }
        mbar_wait(BAR_FREE, par);                 // every CTA freed its hbuf
#pragma unroll
        for (int r = 0; r < 4; r++) {
            uint32_t la = HBa + (uint32_t)(((rg + 16*r)*HROW + j0)*4);
#pragma unroll
            for (int p = 0; p < CLSZ; p++) stc32(la, p, h2v[r]);
        }
        __syncthreads();
        if (tid < CLSZ) { fence_cluster(); mbar_arrive_rank(BAR_H2, tid); }
        mbar_wait(BAR_H2, par);

        // ---- C: q = h2 @ Wq (my 32 cols), route rows to owners ----
        float qa[4];
#pragma unroll
        for (int r = 0; r < 4; r++) qa[r] = 0.f;
        {
            const float* wq = wqs + jt*WROW;
#pragma unroll 4
            for (int k4 = 0; k4 < 64; k4++) {
                float4 bb = *(const float4*)(wq + k4*4);
#pragma unroll
                for (int r = 0; r < 4; r++) {
                    float4 a = *(const float4*)&hbuf[(rg + 16*r)*HROW + k4*4];
                    qa[r] = dot4(a, bb, qa[r]);
                }
            }
        }
#pragma unroll
        for (int r = 0; r < 4; r++) {
            int cr = rg + 16*r;
            uint32_t la = QBa + (uint32_t)(((cr & 7)*256 + j0)*4);
            stc32(la, (uint32_t)(cr >> 3), qa[r]);
        }
        __syncthreads();
        if (tid < CLSZ) { fence_cluster(); mbar_arrive_rank(BAR_Q, tid); }
        for (int i = tid; i < 800; i += NT) su[i] = -1000000000.0f;   // local
        mbar_wait(BAR_Q, par);
        __syncthreads();

        // ---- D: attention on my 8 rows (2 warps/row), argmax, state ----
        {
            const int w2i = w >> 1, parr = w & 1;
            const int R = b0 + w2i;
            float4 q0 = *(const float4*)(qbuf + w2i*256 + lane*4);
            float4 q1 = *(const float4*)(qbuf + w2i*256 + 128 + lane*4);
            float4 v0 = *(const float4*)(sv + lane*4);
            float4 v1 = *(const float4*)(sv + 128 + lane*4);
            const float4* refrow = (const float4*)(REF + (size_t)R*Nn*Hh);
#pragma unroll 1
            for (int n = parr; n < Nn; n += 2) {
                if (mask[w2i*100 + n]) continue;
                float4 r0 = __ldg(refrow + n*64 + lane);
                float4 r1 = __ldg(refrow + n*64 + 32 + lane);
                float s = tanh4dot(q0, r0, v0) + tanh4dot(q1, r1, v1);
#pragma unroll
                for (int o = 16; o; o >>= 1) s += __shfl_xor_sync(~0u, s, o);
                if (lane == 0) su[w2i*100 + n] = 10.f * fast_tanh(s);
            }
        }
        __syncthreads();
        if (w < 8) {
            float best = -INFINITY; int bidx = 0x7fffffff;
            for (int n = lane; n < Nn; n += 32) {
                float u = su[w*100 + n];
                if (u > best) { best = u; bidx = n; }
            }
#pragma unroll
            for (int o = 16; o; o >>= 1) {
                float ov = __shfl_xor_sync(~0u, best, o);
                int   oi = __shfl_xor_sync(~0u, bidx, o);
                if (ov > best || (ov == best && oi < bidx)) { best = ov; bidx = oi; }
            }
            float se = 0.f;
            for (int n = lane; n < Nn; n += 32) se += __expf(su[w*100 + n] - best);
#pragma unroll
            for (int o = 16; o; o >>= 1) se += __shfl_xor_sync(~0u, se, o);
            ll += -__logf(se);
            if (lane == 0) {
                nxt[w] = bidx;
                mask[w*100 + bidx] = 1;
                pi[w*100 + t] = (unsigned char)bidx;
            }
        }
        __syncthreads();
        Dv -= 0.01f;
    }

    // ---- tour cost + output: warp w handles row w (w < 8) ----
    if (w < 8) {
        float cs = 0.f;
        const float* xb = x + (size_t)(b0 + w)*Nn*2;
        for (int tt = lane; tt < Nn; tt += 32) {
            int a  = pi[w*100 + tt];
            int cc = pi[w*100 + ((tt == Nn-1) ? 0 : tt+1)];
            float dx = __ldg(xb + a*2)     - __ldg(xb + cc*2);
            float dy = __ldg(xb + a*2 + 1) - __ldg(xb + cc*2 + 1);
            cs += sqrtf(dx*dx + dy*dy);
        }
#pragma unroll
        for (int o = 16; o; o >>= 1) cs += __shfl_xor_sync(~0u, cs, o);
        if (lane == 0) { out[b0 + w] = cs; out[Bsz + b0 + w] = ll; }
    }
    CLUSTER_SYNC_();   // keep cluster alive until all DSMEM traffic done
}

// ---------------- launcher ----------------
extern "C" void kernel_launch(void* const* d_in, const int* in_sizes, int n_in,
                              void* d_out, int out_size) {
    const float* x     = (const float*)d_in[0];
    const float* enc   = (const float*)d_in[1];
    const float* W_ih1 = (const float*)d_in[2];
    const float* b_ih1 = (const float*)d_in[4];
    const float* b_hh1 = (const float*)d_in[5];
    const float* W_ih2 = (const float*)d_in[6];
    const float* b_ih2 = (const float*)d_in[8];
    const float* b_hh2 = (const float*)d_in[9];
    const float* W_q   = (const float*)d_in[10];
    const float* W_ref = (const float*)d_in[11];
    const float* v     = (const float*)d_in[12];
    float* out = (float*)d_out;

    float *G, *REF, *G0, *MEAN, *W1T, *BIAS0, *WD;
    cudaGetSymbolAddress((void**)&G,    g_G);
    cudaGetSymbolAddress((void**)&REF,  g_ref);
    cudaGetSymbolAddress((void**)&G0,   g_G0);
    cudaGetSymbolAddress((void**)&MEAN, g_mean);
    cudaGetSymbolAddress((void**)&W1T,  g_W1T);
    cudaGetSymbolAddress((void**)&BIAS0,g_bias0);
    cudaGetSymbolAddress((void**)&WD,   g_wD);

    cudaFuncSetAttribute(k_loop, cudaFuncAttributeMaxDynamicSharedMemorySize, SMEM_BYTES);
    cudaFuncSetAttribute(k_loop, cudaFuncAttributeNonPortableClusterSizeAllowed, 1);

    k_prep<<<768, 256>>>(W_ih1, b_ih1);
    k_mean<<<Bsz, 256>>>(enc);
    k_sgemm<128,128,8,8><<<dim3(H3/128, (Bsz*Nn)/128), 256>>>(enc, W1T, b_ih1, G, Bsz*Nn, H3, Hh);
    k_sgemm<128,128,8,8><<<dim3(Hh/128, (Bsz*Nn)/128), 256>>>(enc, W_ref, nullptr, REF, Bsz*Nn, Hh, Hh);
    k_sgemm<64,64,4,4><<<dim3(H3/64, Bsz/64), 256>>>(MEAN, W1T, BIAS0, G0, Bsz, H3, Hh);
    k_loop<<<NBLK, NT, SMEM_BYTES>>>(G, G0, REF, W_ih2, W_q, b_hh1, b_ih2, b_hh2, v, WD, x, out);
}

// round 10
// speedup vs baseline: 2.0330x; 2.0330x over previous
#include <cuda_runtime.h>
#include <math.h>

#define Bsz 1024
#define Nn  100
#define Hh  256
#define H3  768
#define NBLK 128
#define NT  512

// ---------------- static device scratch ----------------
__device__ float g_G[Bsz*Nn*H3];      // enc @ W1T + b_ih1
__device__ float g_ref[Bsz*Nn*Hh];    // enc @ W_ref
__device__ float g_G0[Bsz*H3];
__device__ float g_mean[Bsz*Hh];
__device__ float g_W1T[Hh*H3];        // [k][j] for precompute GEMM
__device__ float g_W2P[H3*Hh];        // packed: [tk][kk4][j][c]  (8 x 8 x 768 x 4)
__device__ float g_WqP[Hh*Hh];        // packed: [tk][kk4][j][c]  (8 x 8 x 256 x 4)
__device__ float g_bias0[H3];
__device__ float g_wD[H3];

// ---------------- math helpers ----------------
__device__ __forceinline__ float fast_tanh(float x) {
    float ax = fabsf(x);
    float e  = __expf(-2.0f * ax);
    float t  = __fdividef(1.0f - e, 1.0f + e);
    return copysignf(t, x);
}
__device__ __forceinline__ float sigmoidf_(float x) {
    return __fdividef(1.0f, 1.0f + __expf(-x));
}
__device__ __forceinline__ float tanh4dot(float4 q, float4 r, float4 v) {
    const float C = -2.8853900817779268f;   // -2*log2(e)
    float x0=q.x+r.x, x1=q.y+r.y, x2=q.z+r.z, x3=q.w+r.w;
    float e0=exp2f(fabsf(x0)*C), e1=exp2f(fabsf(x1)*C);
    float e2=exp2f(fabsf(x2)*C), e3=exp2f(fabsf(x3)*C);
    float a0=1.f+e0, a1=1.f+e1, a2=1.f+e2, a3=1.f+e3;
    float m0=(1.f-e0)*v.x, m1=(1.f-e1)*v.y, m2=(1.f-e2)*v.z, m3=(1.f-e3)*v.w;
    m0=__uint_as_float(__float_as_uint(m0)^(__float_as_uint(x0)&0x80000000u));
    m1=__uint_as_float(__float_as_uint(m1)^(__float_as_uint(x1)&0x80000000u));
    m2=__uint_as_float(__float_as_uint(m2)^(__float_as_uint(x2)&0x80000000u));
    m3=__uint_as_float(__float_as_uint(m3)^(__float_as_uint(x3)&0x80000000u));
    float p01=a0*a1, p23=a2*a3, d=p01*p23, rd;
    asm("rcp.approx.f32 %0, %1;" : "=f"(rd) : "f"(d));
    float num = fmaf(fmaf(m0,a1,m1*a0), p23, fmaf(m2,a3,m3*a2)*p01);
    return num * rd;
}
__device__ __forceinline__ float dot4(float4 a, float4 b, float acc) {
    acc = fmaf(a.x, b.x, acc); acc = fmaf(a.y, b.y, acc);
    acc = fmaf(a.z, b.z, acc); acc = fmaf(a.w, b.w, acc);
    return acc;
}
__device__ __forceinline__ void cp16(float* dst, const float* src) {
    unsigned d = (unsigned)__cvta_generic_to_shared(dst);
    asm volatile("cp.async.cg.shared.global [%0], [%1], 16;" :: "r"(d), "l"(src) : "memory");
}
#define CP_COMMIT() asm volatile("cp.async.commit_group;")
#define CP_WAIT0()  asm volatile("cp.async.wait_group 0;")

// ---------------- precompute kernels ----------------
__global__ void k_prep(const float* __restrict__ W_ih1,
                       const float* __restrict__ W_ih2,
                       const float* __restrict__ W_q,
                       const float* __restrict__ b_ih1) {
    int i = blockIdx.x * 256 + threadIdx.x;    // 768 blocks -> 196608
    if (i < Hh*H3) {
        int k = i / H3, j = i % H3;
        g_W1T[i] = W_ih1[j*257 + k];
        int c = i & 3, tmp = i >> 2;
        int jj = tmp % 768, kk4 = (tmp / 768) & 7, tk = tmp / 6144;
        int kk = tk*32 + kk4*4 + c;
        g_W2P[i] = W_ih2[jj*256 + kk];
    }
    if (i < Hh*Hh) {
        int c = i & 3, tmp = i >> 2;
        int jj = tmp & 255, kk4 = (tmp >> 8) & 7, tk = tmp >> 11;
        int kk = tk*32 + kk4*4 + c;
        g_WqP[i] = W_q[kk*256 + jj];
    }
    if (i < H3) {
        float wd = W_ih1[i*257 + 256];
        g_wD[i] = wd;
        g_bias0[i] = b_ih1[i] + wd;
    }
}

__global__ void k_mean(const float* __restrict__ enc) {
    int b = blockIdx.x, h = threadIdx.x;
    float s = 0.f;
    for (int n = 0; n < Nn; n++) s += enc[(b*Nn + n)*Hh + h];
    g_mean[b*Hh + h] = s / (float)Nn;
}

template<int BM, int BN, int TM, int TN>
__global__ __launch_bounds__(256)
void k_sgemm(const float* __restrict__ A, const float* __restrict__ Bm,
             const float* __restrict__ bias, float* __restrict__ C,
             int M, int N, int K) {
    const int BK = 16;
    __shared__ float As[BK][BM];
    __shared__ float Bs[BK][BN];
    int tid = threadIdx.x;
    int tx = tid % (BN/TN), ty = tid / (BN/TN);
    int m0 = blockIdx.y * BM, n0 = blockIdx.x * BN;
    float acc[TM][TN];
#pragma unroll
    for (int i = 0; i < TM; i++)
#pragma unroll
        for (int j = 0; j < TN; j++) acc[i][j] = 0.f;
    for (int k0 = 0; k0 < K; k0 += BK) {
#pragma unroll
        for (int r = 0; r < (BM*BK)/1024; r++) {
            int idx = tid + r*256, mm = idx/(BK/4), kk4 = idx%(BK/4);
            float4 a = *(const float4*)&A[(size_t)(m0+mm)*K + k0 + kk4*4];
            As[kk4*4+0][mm]=a.x; As[kk4*4+1][mm]=a.y; As[kk4*4+2][mm]=a.z; As[kk4*4+3][mm]=a.w;
        }
#pragma unroll
        for (int r = 0; r < (BK*BN)/1024; r++) {
            int idx = tid + r*256, kk = idx/(BN/4), nn4 = idx%(BN/4);
            *(float4*)&Bs[kk][nn4*4] = *(const float4*)&Bm[(size_t)(k0+kk)*N + n0 + nn4*4];
        }
        __syncthreads();
#pragma unroll
        for (int kk = 0; kk < BK; kk++) {
            float ra[TM], rb[TN];
#pragma unroll
            for (int i = 0; i < TM; i += 4) *(float4*)&ra[i] = *(float4*)&As[kk][ty*TM+i];
#pragma unroll
            for (int j = 0; j < TN; j += 4) *(float4*)&rb[j] = *(float4*)&Bs[kk][tx*TN+j];
#pragma unroll
            for (int i = 0; i < TM; i++)
#pragma unroll
                for (int j = 0; j < TN; j++) acc[i][j] += ra[i]*rb[j];
        }
        __syncthreads();
    }
#pragma unroll
    for (int i = 0; i < TM; i++) {
        int m = m0 + ty*TM + i;
#pragma unroll
        for (int j = 0; j < TN; j += 4) {
            int n = n0 + tx*TN + j;
            float4 r;
            r.x = acc[i][j+0] + (bias ? bias[n+0] : 0.f);
            r.y = acc[i][j+1] + (bias ? bias[n+1] : 0.f);
            r.z = acc[i][j+2] + (bias ? bias[n+2] : 0.f);
            r.w = acc[i][j+3] + (bias ? bias[n+3] : 0.f);
            *(float4*)&C[(size_t)m*N + n] = r;
        }
    }
}

// ---------------- monolithic block-local decode loop ----------------
// smem: shB 2x24576 | h1 2048 | h2 2048 | q 2048 | v 256 | su 800 | nxt 8i | cand 800B | pi 800B
#define SMEM_BYTES ((49152 + 2048*3 + 256 + 800)*4 + 8*4 + 800 + 800)

__global__ __launch_bounds__(NT, 1)
void k_loop(const float* __restrict__ G,  const float* __restrict__ G0,
            const float* __restrict__ REF,
            const float* __restrict__ W2P, const float* __restrict__ WqP,
            const float* __restrict__ b_hh1,
            const float* __restrict__ b_ih2, const float* __restrict__ b_hh2,
            const float* __restrict__ v,   const float* __restrict__ wD,
            const float* __restrict__ x,   float* __restrict__ out) {
    extern __shared__ float sm[];
    float* shB   = sm;                    // 2 x 24576
    float* sh_h1 = sm + 49152;
    float* sh_h2 = sh_h1 + 2048;
    float* sh_q  = sh_h2 + 2048;
    float* sh_v  = sh_q + 2048;
    float* sh_su = sh_v + 256;            // su by LIST POSITION: [row][i]
    int*   sh_nxt = (int*)(sh_su + 800);
    unsigned char* sh_cand = (unsigned char*)(sh_nxt + 8);   // candidate lists
    unsigned char* sh_pi   = sh_cand + 800;

    const int tid = threadIdx.x, lane = tid & 31, w = tid >> 5;
    const int b0 = blockIdx.x * 8;
    // pair mapping: threads (2t,2t+1) share column triplet j0, split rows 0-3 / 4-7
    const int j0 = (tid >> 1) & 255, rh = tid & 1;

    for (int i = tid; i < 800; i += NT) sh_cand[i] = (unsigned char)(i % 100);
    if (tid < 256) sh_v[tid] = __ldg(v + tid);

    const float bi2r = __ldg(b_ih2 + j0),       bh2r = __ldg(b_hh2 + j0);
    const float bi2z = __ldg(b_ih2 + 256 + j0), bh2z = __ldg(b_hh2 + 256 + j0);
    const float bi2n = __ldg(b_ih2 + 512 + j0), bh2n = __ldg(b_hh2 + 512 + j0);

    // prefetch W2P tile0 -> buf0 (24576 floats, 12 float4/thread)
#pragma unroll
    for (int p = 0; p < 12; p++) { int e = tid + p*NT; cp16(shB + e*4, W2P + e*4); }
    CP_COMMIT();
    __syncthreads();

    float Dv = 1.0f, ll = 0.0f;

#pragma unroll 1
    for (int t = 0; t < Nn; t++) {
        // ---- A: GRU1 (h=0) -> sh_h1 ----
#pragma unroll
        for (int c = 0; c < 4; c++) {
            int idx = tid + c*NT;              // 2048 outputs
            int row = idx >> 8, j = idx & 255;
            const float* gsrc = (t == 0) ? (G0 + (size_t)(b0 + row)*H3)
                                         : (G + ((size_t)(b0 + row)*Nn + sh_nxt[row])*H3);
            float gr = __ldg(gsrc+j), gz = __ldg(gsrc+j+256), gn = __ldg(gsrc+j+512);
            if (t > 0) {
                gr = fmaf(Dv, __ldg(wD+j),     gr);
                gz = fmaf(Dv, __ldg(wD+j+256), gz);
                gn = fmaf(Dv, __ldg(wD+j+512), gn);
            }
            float rr = sigmoidf_(gr + __ldg(b_hh1+j));
            float zz = sigmoidf_(gz + __ldg(b_hh1+j+256));
            float nn = fast_tanh(fmaf(rr, __ldg(b_hh1+j+512), gn));
            sh_h1[idx] = (1.f - zz) * nn;
        }
        __syncthreads();

        // ---- B: GEMM2 (gi2 = h1 @ W2T) + fused GRU2 -> sh_h2 ----
        {
            float acc0[4], acc1[4], acc2[4];
#pragma unroll
            for (int r = 0; r < 4; r++) { acc0[r]=0.f; acc1[r]=0.f; acc2[r]=0.f; }
#pragma unroll 1
            for (int tile = 0; tile < 8; tile++) {
                CP_WAIT0();
                __syncthreads();
                if (tile < 7) {
                    const float* src = W2P + (tile+1)*24576;
                    float* dst = shB + ((tile+1)&1)*24576;
#pragma unroll
                    for (int p = 0; p < 12; p++) { int e = tid + p*NT; cp16(dst + e*4, src + e*4); }
                    CP_COMMIT();
                } else {
                    // buf0 free (last read at tile 6): prefetch WqP tile0
#pragma unroll
                    for (int p = 0; p < 4; p++) { int e = tid + p*NT; cp16(shB + e*4, WqP + e*4); }
                    CP_COMMIT();
                }
                const float* Bt = shB + (tile&1)*24576;
#pragma unroll
                for (int kk4 = 0; kk4 < 8; kk4++) {
                    const float* bp = Bt + kk4*3072 + j0*4;
                    float4 bb0 = *(const float4*)bp;
                    float4 bb1 = *(const float4*)(bp + 1024);
                    float4 bb2 = *(const float4*)(bp + 2048);
#pragma unroll
                    for (int r = 0; r < 4; r++) {
                        float4 a = *(const float4*)(sh_h1 + (rh*4+r)*256 + tile*32 + kk4*4);
                        acc0[r] = dot4(a, bb0, acc0[r]);
                        acc1[r] = dot4(a, bb1, acc1[r]);
                        acc2[r] = dot4(a, bb2, acc2[r]);
                    }
                }
            }
#pragma unroll
            for (int r = 0; r < 4; r++) {
                float rr = sigmoidf_((acc0[r] + bi2r) + bh2r);
                float zz = sigmoidf_((acc1[r] + bi2z) + bh2z);
                float nn = fast_tanh(fmaf(rr, bh2n, acc2[r] + bi2n));
                sh_h2[(rh*4+r)*256 + j0] = (1.f - zz) * nn;
            }
        }
        __syncthreads();

        // ---- C: GEMM3 (q = h2 @ Wq) -> sh_q ----
        {
            float qa[4];
#pragma unroll
            for (int r = 0; r < 4; r++) qa[r] = 0.f;
#pragma unroll 1
            for (int tile = 0; tile < 8; tile++) {
                CP_WAIT0();
                __syncthreads();
                if (tile < 7) {
                    const float* src = WqP + (tile+1)*8192;
                    float* dst = shB + ((tile+1)&1)*24576;
#pragma unroll
                    for (int p = 0; p < 4; p++) { int e = tid + p*NT; cp16(dst + e*4, src + e*4); }
                    CP_COMMIT();
                } else {
                    // buf0 free: prefetch next step's W2P tile0
#pragma unroll
                    for (int p = 0; p < 12; p++) { int e = tid + p*NT; cp16(shB + e*4, W2P + e*4); }
                    CP_COMMIT();
                }
                const float* Bt = shB + (tile&1)*24576;
#pragma unroll
                for (int kk4 = 0; kk4 < 8; kk4++) {
                    float4 bb = *(const float4*)(Bt + kk4*1024 + j0*4);
#pragma unroll
                    for (int r = 0; r < 4; r++) {
                        float4 a = *(const float4*)(sh_h2 + (rh*4+r)*256 + tile*32 + kk4*4);
                        qa[r] = dot4(a, bb, qa[r]);
                    }
                }
            }
#pragma unroll
            for (int r = 0; r < 4; r++) sh_q[(rh*4+r)*256 + j0] = qa[r];
        }
        __syncthreads();

        // ---- D: attention over candidate list, 2 warps/row, pipelined loads ----
        {
            const int w2i = w >> 1, parr = w & 1;
            const int cnt = Nn - t;
            const int R = b0 + w2i;
            float4 q0 = *(const float4*)(sh_q + w2i*256 + lane*4);
            float4 q1 = *(const float4*)(sh_q + w2i*256 + 128 + lane*4);
            float4 v0 = *(const float4*)(sh_v + lane*4);
            float4 v1 = *(const float4*)(sh_v + 128 + lane*4);
            const float4* refrow = (const float4*)(REF + (size_t)R*Nn*Hh);
            const unsigned char* cl = sh_cand + w2i*100;
            int i = parr;
            float4 ra, rb;
            if (i < cnt) {
                int n0i = cl[i];
                ra = __ldg(refrow + n0i*64 + lane);
                rb = __ldg(refrow + n0i*64 + 32 + lane);
            }
#pragma unroll 1
            for (; i < cnt; i += 2) {
                int nnx = (i + 2 < cnt) ? cl[i + 2] : 0;
                float4 ra2 = __ldg(refrow + nnx*64 + lane);
                float4 rb2 = __ldg(refrow + nnx*64 + 32 + lane);
                float s = tanh4dot(q0, ra, v0) + tanh4dot(q1, rb, v1);
#pragma unroll
                for (int o = 16; o; o >>= 1) s += __shfl_xor_sync(~0u, s, o);
                if (lane == 0) sh_su[w2i*100 + i] = 10.f * fast_tanh(s);
                ra = ra2; rb = rb2;
            }
        }
        __syncthreads();
        // argmax / log-softmax / state: warp w handles row w (w < 8)
        if (w < 8) {
            const int cnt = Nn - t;
            float best = -INFINITY; int bidx = 0x7fffffff; int bpos = 0;
            for (int i = lane; i < cnt; i += 32) {
                float u = sh_su[w*100 + i];
                int n = sh_cand[w*100 + i];
                if (u > best || (u == best && n < bidx)) { best = u; bidx = n; bpos = i; }
            }
#pragma unroll
            for (int o = 16; o; o >>= 1) {
                float ov = __shfl_xor_sync(~0u, best, o);
                int   oi = __shfl_xor_sync(~0u, bidx, o);
                int   op = __shfl_xor_sync(~0u, bpos, o);
                if (ov > best || (ov == best && oi < bidx)) { best = ov; bidx = oi; bpos = op; }
            }
            float se = 0.f;
            for (int i = lane; i < cnt; i += 32) se += __expf(sh_su[w*100 + i] - best);
#pragma unroll
            for (int o = 16; o; o >>= 1) se += __shfl_xor_sync(~0u, se, o);
            ll += -__logf(se);
            if (lane == 0) {
                sh_nxt[w] = bidx;
                sh_pi[w*100 + t] = (unsigned char)bidx;
                sh_cand[w*100 + bpos] = sh_cand[w*100 + cnt - 1];   // swap-remove
            }
        }
        __syncthreads();
        Dv -= 0.01f;
    }
    CP_WAIT0();
    __syncthreads();

    // ---- tour cost + output: warp w handles row w (w < 8) ----
    if (w < 8) {
        float cs = 0.f;
        const float* xb = x + (size_t)(b0 + w)*Nn*2;
        for (int tt = lane; tt < Nn; tt += 32) {
            int a  = sh_pi[w*100 + tt];
            int cc = sh_pi[w*100 + ((tt == Nn-1) ? 0 : tt+1)];
            float dx = __ldg(xb + a*2)     - __ldg(xb + cc*2);
            float dy = __ldg(xb + a*2 + 1) - __ldg(xb + cc*2 + 1);
            cs += sqrtf(dx*dx + dy*dy);
        }
#pragma unroll
        for (int o = 16; o; o >>= 1) cs += __shfl_xor_sync(~0u, cs, o);
        if (lane == 0) { out[b0 + w] = cs; out[Bsz + b0 + w] = ll; }
    }
}

// ---------------- launcher ----------------
extern "C" void kernel_launch(void* const* d_in, const int* in_sizes, int n_in,
                              void* d_out, int out_size) {
    const float* x     = (const float*)d_in[0];
    const float* enc   = (const float*)d_in[1];
    const float* W_ih1 = (const float*)d_in[2];
    const float* b_ih1 = (const float*)d_in[4];
    const float* b_hh1 = (const float*)d_in[5];
    const float* W_ih2 = (const float*)d_in[6];
    const float* b_ih2 = (const float*)d_in[8];
    const float* b_hh2 = (const float*)d_in[9];
    const float* W_q   = (const float*)d_in[10];
    const float* W_ref = (const float*)d_in[11];
    const float* v     = (const float*)d_in[12];
    float* out = (float*)d_out;

    float *G, *REF, *G0, *MEAN, *W1T, *W2P, *WqP, *BIAS0, *WD;
    cudaGetSymbolAddress((void**)&G,    g_G);
    cudaGetSymbolAddress((void**)&REF,  g_ref);
    cudaGetSymbolAddress((void**)&G0,   g_G0);
    cudaGetSymbolAddress((void**)&MEAN, g_mean);
    cudaGetSymbolAddress((void**)&W1T,  g_W1T);
    cudaGetSymbolAddress((void**)&W2P,  g_W2P);
    cudaGetSymbolAddress((void**)&WqP,  g_WqP);
    cudaGetSymbolAddress((void**)&BIAS0,g_bias0);
    cudaGetSymbolAddress((void**)&WD,   g_wD);

    cudaFuncSetAttribute(k_loop, cudaFuncAttributeMaxDynamicSharedMemorySize, SMEM_BYTES);

    k_prep<<<768, 256>>>(W_ih1, W_ih2, W_q, b_ih1);
    k_mean<<<Bsz, 256>>>(enc);
    k_sgemm<128,128,8,8><<<dim3(H3/128, (Bsz*Nn)/128), 256>>>(enc, W1T, b_ih1, G, Bsz*Nn, H3, Hh);
    k_sgemm<128,128,8,8><<<dim3(Hh/128, (Bsz*Nn)/128), 256>>>(enc, W_ref, nullptr, REF, Bsz*Nn, Hh, Hh);
    k_sgemm<64,64,4,4><<<dim3(H3/64, Bsz/64), 256>>>(MEAN, W1T, BIAS0, G0, Bsz, H3, Hh);
    k_loop<<<NBLK, NT, SMEM_BYTES>>>(G, G0, REF, W2P, WqP, b_hh1, b_ih2, b_hh2, v, WD, x, out);
}

// round 11
// speedup vs baseline: 2.1539x; 1.0594x over previous
#include <cuda_runtime.h>
#include <math.h>
#include <stdint.h>

#define Bsz 1024
#define Nn  100
#define Hh  256
#define H3  768
#define NBLK 128
#define NT  512

// ---------------- static device scratch ----------------
__device__ float g_G[Bsz*Nn*H3];      // enc @ W1T + b_ih1
__device__ float g_ref[Bsz*Nn*Hh];    // enc @ W_ref
__device__ float g_G0[Bsz*H3];
__device__ float g_mean[Bsz*Hh];
__device__ float g_W1T[Hh*H3];        // [k][j] for precompute GEMM
__device__ __align__(256) float g_W2P[H3*Hh];   // packed: [tk][kk4][j][c]
__device__ __align__(256) float g_WqP[Hh*Hh];   // packed: [tk][kk4][j][c]
__device__ float g_bias0[H3];
__device__ float g_wD[H3];

// ---------------- math helpers ----------------
__device__ __forceinline__ float fast_tanh(float x) {
    float ax = fabsf(x);
    float e  = __expf(-2.0f * ax);
    float t  = __fdividef(1.0f - e, 1.0f + e);
    return copysignf(t, x);
}
__device__ __forceinline__ float sigmoidf_(float x) {
    return __fdividef(1.0f, 1.0f + __expf(-x));
}
__device__ __forceinline__ float tanh4dot(float4 q, float4 r, float4 v) {
    const float C = -2.8853900817779268f;   // -2*log2(e)
    float x0=q.x+r.x, x1=q.y+r.y, x2=q.z+r.z, x3=q.w+r.w;
    float e0=exp2f(fabsf(x0)*C), e1=exp2f(fabsf(x1)*C);
    float e2=exp2f(fabsf(x2)*C), e3=exp2f(fabsf(x3)*C);
    float a0=1.f+e0, a1=1.f+e1, a2=1.f+e2, a3=1.f+e3;
    float m0=(1.f-e0)*v.x, m1=(1.f-e1)*v.y, m2=(1.f-e2)*v.z, m3=(1.f-e3)*v.w;
    m0=__uint_as_float(__float_as_uint(m0)^(__float_as_uint(x0)&0x80000000u));
    m1=__uint_as_float(__float_as_uint(m1)^(__float_as_uint(x1)&0x80000000u));
    m2=__uint_as_float(__float_as_uint(m2)^(__float_as_uint(x2)&0x80000000u));
    m3=__uint_as_float(__float_as_uint(m3)^(__float_as_uint(x3)&0x80000000u));
    float p01=a0*a1, p23=a2*a3, d=p01*p23, rd;
    asm("rcp.approx.f32 %0, %1;" : "=f"(rd) : "f"(d));
    float num = fmaf(fmaf(m0,a1,m1*a0), p23, fmaf(m2,a3,m3*a2)*p01);
    return num * rd;
}
__device__ __forceinline__ float dot4(float4 a, float4 b, float acc) {
    acc = fmaf(a.x, b.x, acc); acc = fmaf(a.y, b.y, acc);
    acc = fmaf(a.z, b.z, acc); acc = fmaf(a.w, b.w, acc);
    return acc;
}

// ---------------- TMA-bulk / mbarrier helpers ----------------
__device__ __forceinline__ uint32_t smem_u32(const void* p) {
    uint32_t a;
    asm("{ .reg .u64 t; cvta.to.shared.u64 t, %1; cvt.u32.u64 %0, t; }" : "=r"(a) : "l"(p));
    return a;
}
__device__ __forceinline__ void mbar_init(uint32_t a, uint32_t cnt) {
    asm volatile("mbarrier.init.shared.b64 [%0], %1;" :: "r"(a), "r"(cnt) : "memory");
}
__device__ __forceinline__ void mbar_expect_tx(uint32_t a, uint32_t bytes) {
    asm volatile("mbarrier.arrive.expect_tx.shared.b64 _, [%0], %1;" :: "r"(a), "r"(bytes) : "memory");
}
__device__ __forceinline__ void bulk_g2s(uint32_t dst, const float* src, uint32_t bytes, uint32_t mbar) {
    asm volatile("cp.async.bulk.shared::cluster.global.mbarrier::complete_tx::bytes [%0], [%1], %2, [%3];"
                 :: "r"(dst), "l"(src), "r"(bytes), "r"(mbar) : "memory");
}
__device__ __forceinline__ void mbar_wait(uint32_t a, uint32_t par) {
    asm volatile("{ .reg .pred P; WL%=:"
                 " mbarrier.try_wait.parity.acquire.cta.shared::cta.b64 P, [%0], %1, 0x989680;"
                 " @P bra WD%=; bra WL%=; WD%=: }"
                 :: "r"(a), "r"(par) : "memory");
}

// ---------------- precompute kernels ----------------
__global__ void k_prep(const float* __restrict__ W_ih1,
                       const float* __restrict__ W_ih2,
                       const float* __restrict__ W_q,
                       const float* __restrict__ b_ih1) {
    int i = blockIdx.x * 256 + threadIdx.x;    // 768 blocks -> 196608
    if (i < Hh*H3) {
        int k = i / H3, j = i % H3;
        g_W1T[i] = W_ih1[j*257 + k];
        int c = i & 3, tmp = i >> 2;
        int jj = tmp % 768, kk4 = (tmp / 768) & 7, tk = tmp / 6144;
        int kk = tk*32 + kk4*4 + c;
        g_W2P[i] = W_ih2[jj*256 + kk];
    }
    if (i < Hh*Hh) {
        int c = i & 3, tmp = i >> 2;
        int jj = tmp & 255, kk4 = (tmp >> 8) & 7, tk = tmp >> 11;
        int kk = tk*32 + kk4*4 + c;
        g_WqP[i] = W_q[kk*256 + jj];
    }
    if (i < H3) {
        float wd = W_ih1[i*257 + 256];
        g_wD[i] = wd;
        g_bias0[i] = b_ih1[i] + wd;
    }
}

__global__ void k_mean(const float* __restrict__ enc) {
    int b = blockIdx.x, h = threadIdx.x;
    float s = 0.f;
    for (int n = 0; n < Nn; n++) s += enc[(b*Nn + n)*Hh + h];
    g_mean[b*Hh + h] = s / (float)Nn;
}

template<int BM, int BN, int TM, int TN>
__global__ __launch_bounds__(256)
void k_sgemm(const float* __restrict__ A, const float* __restrict__ Bm,
             const float* __restrict__ bias, float* __restrict__ C,
             int M, int N, int K) {
    const int BK = 16;
    __shared__ float As[BK][BM];
    __shared__ float Bs[BK][BN];
    int tid = threadIdx.x;
    int tx = tid % (BN/TN), ty = tid / (BN/TN);
    int m0 = blockIdx.y * BM, n0 = blockIdx.x * BN;
    float acc[TM][TN];
#pragma unroll
    for (int i = 0; i < TM; i++)
#pragma unroll
        for (int j = 0; j < TN; j++) acc[i][j] = 0.f;
    for (int k0 = 0; k0 < K; k0 += BK) {
#pragma unroll
        for (int r = 0; r < (BM*BK)/1024; r++) {
            int idx = tid + r*256, mm = idx/(BK/4), kk4 = idx%(BK/4);
            float4 a = *(const float4*)&A[(size_t)(m0+mm)*K + k0 + kk4*4];
            As[kk4*4+0][mm]=a.x; As[kk4*4+1][mm]=a.y; As[kk4*4+2][mm]=a.z; As[kk4*4+3][mm]=a.w;
        }
#pragma unroll
        for (int r = 0; r < (BK*BN)/1024; r++) {
            int idx = tid + r*256, kk = idx/(BN/4), nn4 = idx%(BN/4);
            *(float4*)&Bs[kk][nn4*4] = *(const float4*)&Bm[(size_t)(k0+kk)*N + n0 + nn4*4];
        }
        __syncthreads();
#pragma unroll
        for (int kk = 0; kk < BK; kk++) {
            float ra[TM], rb[TN];
#pragma unroll
            for (int i = 0; i < TM; i += 4) *(float4*)&ra[i] = *(float4*)&As[kk][ty*TM+i];
#pragma unroll
            for (int j = 0; j < TN; j += 4) *(float4*)&rb[j] = *(float4*)&Bs[kk][tx*TN+j];
#pragma unroll
            for (int i = 0; i < TM; i++)
#pragma unroll
                for (int j = 0; j < TN; j++) acc[i][j] += ra[i]*rb[j];
        }
        __syncthreads();
    }
#pragma unroll
    for (int i = 0; i < TM; i++) {
        int m = m0 + ty*TM + i;
#pragma unroll
        for (int j = 0; j < TN; j += 4) {
            int n = n0 + tx*TN + j;
            float4 r;
            r.x = acc[i][j+0] + (bias ? bias[n+0] : 0.f);
            r.y = acc[i][j+1] + (bias ? bias[n+1] : 0.f);
            r.z = acc[i][j+2] + (bias ? bias[n+2] : 0.f);
            r.w = acc[i][j+3] + (bias ? bias[n+3] : 0.f);
            *(float4*)&C[(size_t)m*N + n] = r;
        }
    }
}

// ---------------- monolithic block-local decode loop ----------------
// smem: shB 2x24576 | h1 2048 | h2 2048 | q 2048 | v 256 | su 800 | nxt 8i | cand 800B | pi 800B | mbar 16B
#define FLOATS_MAIN (49152 + 2048*3 + 256 + 800)
#define MBAR_OFF_BYTES (FLOATS_MAIN*4 + 8*4 + 800 + 800)   // 227040, 8-aligned
#define SMEM_BYTES (MBAR_OFF_BYTES + 16)
#define NTILES_TOTAL (Nn*16)

__global__ __launch_bounds__(NT, 1)
void k_loop(const float* __restrict__ G,  const float* __restrict__ G0,
            const float* __restrict__ REF,
            const float* __restrict__ W2P, const float* __restrict__ WqP,
            const float* __restrict__ b_hh1,
            const float* __restrict__ b_ih2, const float* __restrict__ b_hh2,
            const float* __restrict__ v,   const float* __restrict__ wD,
            const float* __restrict__ x,   float* __restrict__ out) {
    extern __shared__ float sm[];
    float* shB   = sm;                    // 2 x 24576
    float* sh_h1 = sm + 49152;
    float* sh_h2 = sh_h1 + 2048;
    float* sh_q  = sh_h2 + 2048;
    float* sh_v  = sh_q + 2048;
    float* sh_su = sh_v + 256;            // su by LIST POSITION: [row][i]
    int*   sh_nxt = (int*)(sh_su + 800);
    unsigned char* sh_cand = (unsigned char*)(sh_nxt + 8);   // candidate lists
    unsigned char* sh_pi   = sh_cand + 800;

    const uint32_t base = smem_u32(sm);
    const uint32_t SHBa = base;
    const uint32_t MB   = base + MBAR_OFF_BYTES;   // 2 mbarriers

    const int tid = threadIdx.x, lane = tid & 31, w = tid >> 5;
    const int b0 = blockIdx.x * 8;
    // pair mapping: threads (2t,2t+1) share column triplet j0, split rows 0-3 / 4-7
    const int j0 = (tid >> 1) & 255, rh = tid & 1;

    for (int i = tid; i < 800; i += NT) sh_cand[i] = (unsigned char)(i % 100);
    if (tid < 256) sh_v[tid] = __ldg(v + tid);

    const float bi2r = __ldg(b_ih2 + j0),       bh2r = __ldg(b_hh2 + j0);
    const float bi2z = __ldg(b_ih2 + 256 + j0), bh2z = __ldg(b_hh2 + 256 + j0);
    const float bi2n = __ldg(b_ih2 + 512 + j0), bh2n = __ldg(b_hh2 + 512 + j0);

    // ---- weight tile stream: g = 16*t + i ; i<8 -> W2P 96KB ; i>=8 -> WqP 32KB ----
    // buffer = g&1 ; wait parity = (g>>1)&1 ; after consuming g, refill same buffer with g+2.
    if (tid == 0) {
        mbar_init(MB, 1);
        mbar_init(MB + 8, 1);
    }
    __syncthreads();
    if (tid == 0) {
        // issue g=0 (W2P tile0 -> buf0) and g=1 (W2P tile1 -> buf1)
        mbar_expect_tx(MB, 98304u);
        bulk_g2s(SHBa, W2P, 98304u, MB);
        mbar_expect_tx(MB + 8, 98304u);
        bulk_g2s(SHBa + 98304u, W2P + 24576, 98304u, MB + 8);
    }

    float Dv = 1.0f, ll = 0.0f;

#pragma unroll 1
    for (int t = 0; t < Nn; t++) {
        // ---- A: GRU1 (h=0) -> sh_h1 ----
#pragma unroll
        for (int c = 0; c < 4; c++) {
            int idx = tid + c*NT;              // 2048 outputs
            int row = idx >> 8, j = idx & 255;
            const float* gsrc = (t == 0) ? (G0 + (size_t)(b0 + row)*H3)
                                         : (G + ((size_t)(b0 + row)*Nn + sh_nxt[row])*H3);
            float gr = __ldg(gsrc+j), gz = __ldg(gsrc+j+256), gn = __ldg(gsrc+j+512);
            if (t > 0) {
                gr = fmaf(Dv, __ldg(wD+j),     gr);
                gz = fmaf(Dv, __ldg(wD+j+256), gz);
                gn = fmaf(Dv, __ldg(wD+j+512), gn);
            }
            float rr = sigmoidf_(gr + __ldg(b_hh1+j));
            float zz = sigmoidf_(gz + __ldg(b_hh1+j+256));
            float nn = fast_tanh(fmaf(rr, __ldg(b_hh1+j+512), gn));
            sh_h1[idx] = (1.f - zz) * nn;
        }
        __syncthreads();

        // ---- B: GEMM2 (gi2 = h1 @ W2T) + fused GRU2 -> sh_h2 ----
        {
            float acc0[4], acc1[4], acc2[4];
#pragma unroll
            for (int r = 0; r < 4; r++) { acc0[r]=0.f; acc1[r]=0.f; acc2[r]=0.f; }
#pragma unroll 1
            for (int tile = 0; tile < 8; tile++) {
                const int g = t*16 + tile;
                mbar_wait(MB + (g&1)*8, (g>>1)&1);
                const float* Bt = shB + (g&1)*24576;
#pragma unroll
                for (int kk4 = 0; kk4 < 8; kk4++) {
                    const float* bp = Bt + kk4*3072 + j0*4;
                    float4 bb0 = *(const float4*)bp;
                    float4 bb1 = *(const float4*)(bp + 1024);
                    float4 bb2 = *(const float4*)(bp + 2048);
#pragma unroll
                    for (int r = 0; r < 4; r++) {
                        float4 a = *(const float4*)(sh_h1 + (rh*4+r)*256 + tile*32 + kk4*4);
                        acc0[r] = dot4(a, bb0, acc0[r]);
                        acc1[r] = dot4(a, bb1, acc1[r]);
                        acc2[r] = dot4(a, bb2, acc2[r]);
                    }
                }
                __syncthreads();                 // all done reading this buffer
                if (tid == 0 && g + 2 < NTILES_TOTAL) {
                    const int g2 = g + 2, s2 = g2 & 15;
                    if (s2 < 8) {
                        mbar_expect_tx(MB + (g2&1)*8, 98304u);
                        bulk_g2s(SHBa + (g2&1)*98304u, W2P + s2*24576, 98304u, MB + (g2&1)*8);
                    } else {
                        mbar_expect_tx(MB + (g2&1)*8, 32768u);
                        bulk_g2s(SHBa + (g2&1)*98304u, WqP + (s2-8)*8192, 32768u, MB + (g2&1)*8);
                    }
                }
            }
#pragma unroll
            for (int r = 0; r < 4; r++) {
                float rr = sigmoidf_((acc0[r] + bi2r) + bh2r);
                float zz = sigmoidf_((acc1[r] + bi2z) + bh2z);
                float nn = fast_tanh(fmaf(rr, bh2n, acc2[r] + bi2n));
                sh_h2[(rh*4+r)*256 + j0] = (1.f - zz) * nn;
            }
        }
        __syncthreads();

        // ---- C: GEMM3 (q = h2 @ Wq) -> sh_q ----
        {
            float qa[4];
#pragma unroll
            for (int r = 0; r < 4; r++) qa[r] = 0.f;
#pragma unroll 1
            for (int tile = 0; tile < 8; tile++) {
                const int g = t*16 + 8 + tile;
                mbar_wait(MB + (g&1)*8, (g>>1)&1);
                const float* Bt = shB + (g&1)*24576;
#pragma unroll
                for (int kk4 = 0; kk4 < 8; kk4++) {
                    float4 bb = *(const float4*)(Bt + kk4*1024 + j0*4);
#pragma unroll
                    for (int r = 0; r < 4; r++) {
                        float4 a = *(const float4*)(sh_h2 + (rh*4+r)*256 + tile*32 + kk4*4);
                        qa[r] = dot4(a, bb, qa[r]);
                    }
                }
                __syncthreads();
                if (tid == 0 && g + 2 < NTILES_TOTAL) {
                    const int g2 = g + 2, s2 = g2 & 15;
                    if (s2 < 8) {
                        mbar_expect_tx(MB + (g2&1)*8, 98304u);
                        bulk_g2s(SHBa + (g2&1)*98304u, W2P + s2*24576, 98304u, MB + (g2&1)*8);
                    } else {
                        mbar_expect_tx(MB + (g2&1)*8, 32768u);
                        bulk_g2s(SHBa + (g2&1)*98304u, WqP + (s2-8)*8192, 32768u, MB + (g2&1)*8);
                    }
                }
            }
#pragma unroll
            for (int r = 0; r < 4; r++) sh_q[(rh*4+r)*256 + j0] = qa[r];
        }
        __syncthreads();

        // ---- D: attention over candidate list, 2 warps/row, pipelined loads ----
        {
            const int w2i = w >> 1, parr = w & 1;
            const int cnt = Nn - t;
            const int R = b0 + w2i;
            float4 q0 = *(const float4*)(sh_q + w2i*256 + lane*4);
            float4 q1 = *(const float4*)(sh_q + w2i*256 + 128 + lane*4);
            float4 v0 = *(const float4*)(sh_v + lane*4);
            float4 v1 = *(const float4*)(sh_v + 128 + lane*4);
            const float4* refrow = (const float4*)(REF + (size_t)R*Nn*Hh);
            const unsigned char* cl = sh_cand + w2i*100;
            int i = parr;
            float4 ra, rb;
            if (i < cnt) {
                int n0i = cl[i];
                ra = __ldg(refrow + n0i*64 + lane);
                rb = __ldg(refrow + n0i*64 + 32 + lane);
            }
#pragma unroll 1
            for (; i < cnt; i += 2) {
                int nnx = (i + 2 < cnt) ? cl[i + 2] : 0;
                float4 ra2 = __ldg(refrow + nnx*64 + lane);
                float4 rb2 = __ldg(refrow + nnx*64 + 32 + lane);
                float s = tanh4dot(q0, ra, v0) + tanh4dot(q1, rb, v1);
#pragma unroll
                for (int o = 16; o; o >>= 1) s += __shfl_xor_sync(~0u, s, o);
                if (lane == 0) sh_su[w2i*100 + i] = 10.f * fast_tanh(s);
                ra = ra2; rb = rb2;
            }
        }
        __syncthreads();
        // argmax / log-softmax / state: warp w handles row w (w < 8)
        if (w < 8) {
            const int cnt = Nn - t;
            float best = -INFINITY; int bidx = 0x7fffffff; int bpos = 0;
            for (int i = lane; i < cnt; i += 32) {
                float u = sh_su[w*100 + i];
                int n = sh_cand[w*100 + i];
                if (u > best || (u == best && n < bidx)) { best = u; bidx = n; bpos = i; }
            }
#pragma unroll
            for (int o = 16; o; o >>= 1) {
                float ov = __shfl_xor_sync(~0u, best, o);
                int   oi = __shfl_xor_sync(~0u, bidx, o);
                int   op = __shfl_xor_sync(~0u, bpos, o);
                if (ov > best || (ov == best && oi < bidx)) { best = ov; bidx = oi; bpos = op; }
            }
            float se = 0.f;
            for (int i = lane; i < cnt; i += 32) se += __expf(sh_su[w*100 + i] - best);
#pragma unroll
            for (int o = 16; o; o >>= 1) se += __shfl_xor_sync(~0u, se, o);
            ll += -__logf(se);
            if (lane == 0) {
                sh_nxt[w] = bidx;
                sh_pi[w*100 + t] = (unsigned char)bidx;
                sh_cand[w*100 + bpos] = sh_cand[w*100 + cnt - 1];   // swap-remove
            }
        }
        __syncthreads();
        Dv -= 0.01f;
    }

    // ---- tour cost + output: warp w handles row w (w < 8) ----
    if (w < 8) {
        float cs = 0.f;
        const float* xb = x + (size_t)(b0 + w)*Nn*2;
        for (int tt = lane; tt < Nn; tt += 32) {
            int a  = sh_pi[w*100 + tt];
            int cc = sh_pi[w*100 + ((tt == Nn-1) ? 0 : tt+1)];
            float dx = __ldg(xb + a*2)     - __ldg(xb + cc*2);
            float dy = __ldg(xb + a*2 + 1) - __ldg(xb + cc*2 + 1);
            cs += sqrtf(dx*dx + dy*dy);
        }
#pragma unroll
        for (int o = 16; o; o >>= 1) cs += __shfl_xor_sync(~0u, cs, o);
        if (lane == 0) { out[b0 + w] = cs; out[Bsz + b0 + w] = ll; }
    }
}

// ---------------- launcher ----------------
extern "C" void kernel_launch(void* const* d_in, const int* in_sizes, int n_in,
                              void* d_out, int out_size) {
    const float* x     = (const float*)d_in[0];
    const float* enc   = (const float*)d_in[1];
    const float* W_ih1 = (const float*)d_in[2];
    const float* b_ih1 = (const float*)d_in[4];
    const float* b_hh1 = (const float*)d_in[5];
    const float* W_ih2 = (const float*)d_in[6];
    const float* b_ih2 = (const float*)d_in[8];
    const float* b_hh2 = (const float*)d_in[9];
    const float* W_q   = (const float*)d_in[10];
    const float* W_ref = (const float*)d_in[11];
    const float* v     = (const float*)d_in[12];
    float* out = (float*)d_out;

    float *G, *REF, *G0, *MEAN, *W1T, *W2P, *WqP, *BIAS0, *WD;
    cudaGetSymbolAddress((void**)&G,    g_G);
    cudaGetSymbolAddress((void**)&REF,  g_ref);
    cudaGetSymbolAddress((void**)&G0,   g_G0);
    cudaGetSymbolAddress((void**)&MEAN, g_mean);
    cudaGetSymbolAddress((void**)&W1T,  g_W1T);
    cudaGetSymbolAddress((void**)&W2P,  g_W2P);
    cudaGetSymbolAddress((void**)&WqP,  g_WqP);
    cudaGetSymbolAddress((void**)&BIAS0,g_bias0);
    cudaGetSymbolAddress((void**)&WD,   g_wD);

    cudaFuncSetAttribute(k_loop, cudaFuncAttributeMaxDynamicSharedMemorySize, SMEM_BYTES);

    k_prep<<<768, 256>>>(W_ih1, W_ih2, W_q, b_ih1);
    k_mean<<<Bsz, 256>>>(enc);
    k_sgemm<128,128,8,8><<<dim3(H3/128, (Bsz*Nn)/128), 256>>>(enc, W1T, b_ih1, G, Bsz*Nn, H3, Hh);
    k_sgemm<128,128,8,8><<<dim3(Hh/128, (Bsz*Nn)/128), 256>>>(enc, W_ref, nullptr, REF, Bsz*Nn, Hh, Hh);
    k_sgemm<64,64,4,4><<<dim3(H3/64, Bsz/64), 256>>>(MEAN, W1T, BIAS0, G0, Bsz, H3, Hh);
    k_loop<<<NBLK, NT, SMEM_BYTES>>>(G, G0, REF, W2P, WqP, b_hh1, b_ih2, b_hh2, v, WD, x, out);
}